// round 1
// baseline (speedup 1.0000x reference)
#include <cuda_runtime.h>
#include <cstdint>

// Problem constants
#define Hh 128
#define Ww 128
#define LL 16384          // H*W
#define NB 2
#define NC1 64            // lv1 channels
#define NC2 128           // lv2 channels

// T_lv2 element count = 2*128*128*128
#define OUT_LV2_ELEMS 4194304

// Scratch (static __device__ arrays: allowed; no runtime allocation)
__device__ int    g_idx[NB * LL];                       // 128 KB
__device__ float4 g_blk[(size_t)NB * (NC1 / 2) * LL * 2]; // 33.5 MB: [b][cp][mh*128+mw][j]

// ---------------------------------------------------------------------------
// Kernel 1: extract NN index as int32. Handles both int64 and int32 source
// (jax may canonicalize int64->int32). Detection: if every odd 32-bit word of
// the first 32768 words is zero, the buffer is int64 (values < 16384).
// Single block so the decision is made with one __syncthreads.
// ---------------------------------------------------------------------------
__global__ void k_idx(const int* __restrict__ hw) {
    __shared__ int s_or;
    if (threadIdx.x == 0) s_or = 0;
    __syncthreads();
    int acc = 0;
    for (int i = threadIdx.x; i < NB * LL / 2; i += blockDim.x)
        acc |= hw[2 * i + 1];               // reads words [1..32767]: safe for both dtypes
    if (acc) atomicOr(&s_or, 1);
    __syncthreads();
    const int stride = s_or ? 1 : 2;        // 1 -> int32 buffer, 2 -> int64 buffer (low words)
    for (int i = threadIdx.x; i < NB * LL; i += blockDim.x)
        g_idx[i] = hw[i * stride];
}

// ---------------------------------------------------------------------------
// Kernel 2: space-to-depth + channel-pair blocking of lv1.
// g_blk slot i = ((b*32+cp)*16384 + mh*128+mw); two float4 per slot:
//   q[0] = channel 2cp   2x2 block rows (2mh,2mh+1), cols (2mw,2mw+1)
//   q[1] = channel 2cp+1 same block
// One 32B unit per (coarse cell, channel pair) => perfect-sector gathers later.
// ---------------------------------------------------------------------------
__global__ void k_blk(const float* __restrict__ lv1) {
    int i = blockIdx.x * blockDim.x + threadIdx.x;   // slot over NB*32*LL = 1,048,576
    int mw  = i & 127;
    int mh  = (i >> 7) & 127;
    int bcp = i >> 14;                // b*32 + cp
    int cp  = bcp & 31;
    int b   = bcp >> 5;
    const float* p0 = lv1 + (((size_t)(b * NC1 + cp * 2)) << 16) + (mh << 9) + (mw << 1);
    float2 r00 = *(const float2*)(p0);
    float2 r01 = *(const float2*)(p0 + 256);
    const float* p1 = p0 + (1 << 16);
    float2 r10 = *(const float2*)(p1);
    float2 r11 = *(const float2*)(p1 + 256);
    float4* q = g_blk + ((size_t)i << 1);
    q[0] = make_float4(r00.x, r00.y, r01.x, r01.y);
    q[1] = make_float4(r10.x, r10.y, r11.x, r11.y);
}

// ---------------------------------------------------------------------------
// Kernel 3: T_lv2. Block = (b, channel pair). Whole float2 plane (128KB) in
// dynamic SMEM; random 9-tap gathers become LDS.64. Index reads are coalesced
// and L1-hot (shared across all channel blocks of the same b).
// ---------------------------------------------------------------------------
__global__ void k_lv2(const float* __restrict__ lv2, float* __restrict__ out) {
    extern __shared__ float2 s_plane[];              // 16384 float2 = 128 KB
    int bcp = blockIdx.x;                            // b*64 + cp
    int cp  = bcp & 63;
    int b   = bcp >> 6;
    const float* base0 = lv2 + ((size_t)(b * NC2 + cp * 2) << 14);
    for (int i = threadIdx.x; i < LL; i += blockDim.x)
        s_plane[i] = make_float2(base0[i], base0[i + LL]);
    __syncthreads();

    const int* idxb = g_idx + (b << 14);
    float* out0 = out + ((size_t)(b * NC2 + cp * 2) << 14);
    const float inv9 = 1.0f / 9.0f;

    for (int p = threadIdx.x; p < LL; p += blockDim.x) {
        int y = p >> 7, x = p & 127;
        float a0 = 0.f, a1 = 0.f;
#pragma unroll
        for (int dy = -1; dy <= 1; dy++) {
#pragma unroll
            for (int dx = -1; dx <= 1; dx++) {
                int oy = y - dy, ox = x - dx;
                if ((unsigned)oy < Hh && (unsigned)ox < Ww) {
                    int m  = idxb[(oy << 7) + ox];
                    int sr = (m >> 7)  + dy;
                    int sc = (m & 127) + dx;
                    if ((unsigned)sr < Hh && (unsigned)sc < Ww) {
                        float2 v = s_plane[(sr << 7) + sc];
                        a0 += v.x; a1 += v.y;
                    }
                }
            }
        }
        out0[p]      = a0 * inv9;
        out0[p + LL] = a1 * inv9;
    }
}

// ---------------------------------------------------------------------------
// Kernel 4: T_lv1. Thread = (b, channel pair, coarse cell (u,v)).
// 9 coalesced idx loads + 9 x 32B perfect-sector gathers from g_blk (L2-hot),
// producing the 2x2 output block for two channels (8 outputs, 4 float2 stores).
// ---------------------------------------------------------------------------
__global__ void k_lv1(float* __restrict__ out) {
    int bid   = blockIdx.x;           // 2*32*16 = 1024 blocks
    int chunk = bid & 15;
    int bcp   = bid >> 4;             // b*32 + cp
    int cp    = bcp & 31;
    int b     = bcp >> 5;
    const int*    idxb = g_idx + (b << 14);
    const float4* blk  = g_blk + ((size_t)bcp << 15);  // bcp * LL * 2
    float* outc0 = out + ((size_t)(b * NC1 + cp * 2) << 16);
    const float inv9 = 1.0f / 9.0f;

#pragma unroll
    for (int it = 0; it < 4; it++) {
        int e = (chunk << 10) + (it << 8) + threadIdx.x;
        int u = e >> 7, v = e & 127;
        float4 A0 = make_float4(0.f, 0.f, 0.f, 0.f);
        float4 A1 = make_float4(0.f, 0.f, 0.f, 0.f);
#pragma unroll
        for (int dy = -1; dy <= 1; dy++) {
#pragma unroll
            for (int dx = -1; dx <= 1; dx++) {
                int ou = u - dy, ov = v - dx;
                if ((unsigned)ou < Hh && (unsigned)ov < Ww) {
                    int m  = idxb[(ou << 7) + ov];
                    int sh = (m >> 7)  + dy;
                    int sw = (m & 127) + dx;
                    if ((unsigned)sh < Hh && (unsigned)sw < Ww) {
                        const float4* q = blk + ((size_t)((sh << 7) + sw) << 1);
                        float4 q0 = q[0];
                        float4 q1 = q[1];
                        A0.x += q0.x; A0.y += q0.y; A0.z += q0.z; A0.w += q0.w;
                        A1.x += q1.x; A1.y += q1.y; A1.z += q1.z; A1.w += q1.w;
                    }
                }
            }
        }
        float* o0 = outc0 + (u << 9) + (v << 1);   // row 2u, col 2v
        *(float2*)(o0)       = make_float2(A0.x * inv9, A0.y * inv9);
        *(float2*)(o0 + 256) = make_float2(A0.z * inv9, A0.w * inv9);
        float* o1 = o0 + (1 << 16);                // channel 2cp+1
        *(float2*)(o1)       = make_float2(A1.x * inv9, A1.y * inv9);
        *(float2*)(o1 + 256) = make_float2(A1.z * inv9, A1.w * inv9);
    }
}

// ---------------------------------------------------------------------------
extern "C" void kernel_launch(void* const* d_in, const int* in_sizes, int n_in,
                              void* d_out, int out_size) {
    // Map inputs by element count (robust to ordering).
    const float* lv1 = nullptr;   // 2*64*256*256  = 8388608
    const float* lv2 = nullptr;   // 2*128*128*128 = 4194304
    const int*   hix = nullptr;   // 2*16384       = 32768
    for (int i = 0; i < n_in; i++) {
        if (in_sizes[i] == 8388608)      lv1 = (const float*)d_in[i];
        else if (in_sizes[i] == 4194304) lv2 = (const float*)d_in[i];
        else if (in_sizes[i] == 32768)   hix = (const int*)d_in[i];
    }
    float* out = (float*)d_out;

    cudaFuncSetAttribute(k_lv2, cudaFuncAttributeMaxDynamicSharedMemorySize, 131072);

    k_idx<<<1, 1024>>>(hix);
    k_blk<<<4096, 256>>>(lv1);
    k_lv2<<<128, 512, 131072>>>(lv2, out);
    k_lv1<<<1024, 256>>>(out + OUT_LV2_ELEMS);
}